// round 1
// baseline (speedup 1.0000x reference)
#include <cuda_runtime.h>
#include <math.h>

// ----------------------------------------------------------------------------
// SpectralPooling: x (8,32,64,64,64) fp32
//   y = idctn( pad( crop( dctn(x) ) ) )
// DCTs along axes 0,1 cancel (orthonormal, crop/pad acts only on axes 2-4).
// Remaining op: per 256 batches, apply B (32x64) along each of last 3 axes,
// where B = D32c^T @ D64c, D32c = dct_mat(32)[:28,:], D64c = dct_mat(64)[:28,:].
// ----------------------------------------------------------------------------

#define NBATCH 256
#define NI 64      // input axis length
#define NO 32      // output axis length

// B stored transposed: g_Bt[i*32 + o] = B[o][i]
__device__ float g_Bt[NI * NO];

// scratch: W[b][i0][o1*32+o2]  (256 * 64 * 1024 floats = 64 MB)
__device__ float g_W[NBATCH * NI * NO * NO];

// ---------------- packed f32x2 helpers (FFMA2: 2 FMA / instr) ----------------
__device__ __forceinline__ unsigned long long ffma2(unsigned long long a,
                                                    unsigned long long b,
                                                    unsigned long long c) {
    unsigned long long d;
    asm("fma.rn.f32x2 %0, %1, %2, %3;" : "=l"(d) : "l"(a), "l"(b), "l"(c));
    return d;
}
__device__ __forceinline__ unsigned long long packdup(float v) {
    unsigned long long r;
    asm("mov.b64 %0, {%1, %1};" : "=l"(r) : "r"(__float_as_uint(v)));
    return r;
}
__device__ __forceinline__ float2 unpack2(unsigned long long v) {
    unsigned lo, hi;
    asm("mov.b64 {%0, %1}, %2;" : "=r"(lo), "=r"(hi) : "l"(v));
    float2 f;
    f.x = __uint_as_float(lo);
    f.y = __uint_as_float(hi);
    return f;
}

// ---------------- init: compute B in double precision -------------------------
__global__ void init_B_kernel() {
    int idx = blockIdx.x * blockDim.x + threadIdx.x;   // 0..2047
    if (idx >= NI * NO) return;
    int i = idx >> 5;   // input index 0..63
    int o = idx & 31;   // output index 0..31
    const double PI = 3.14159265358979323846;
    double s = 0.0;
    for (int k = 0; k < 28; ++k) {
        double s32 = (k == 0) ? sqrt(1.0 / 32.0) : sqrt(2.0 / 32.0);
        double s64 = (k == 0) ? sqrt(1.0 / 64.0) : sqrt(2.0 / 64.0);
        double d32 = s32 * cos(PI * (2.0 * o + 1.0) * (double)k / 64.0);
        double d64 = s64 * cos(PI * (2.0 * i + 1.0) * (double)k / 128.0);
        s += d32 * d64;
    }
    g_Bt[idx] = (float)s;
}

// ---------------- kernel A: fuse contractions over i2 then i1 -----------------
// One CTA per (batch, i0): load slice S[64][64], compute W = B S B^T (32x32),
// write to g_W[b][i0][o1*32+o2].
__global__ __launch_bounds__(256) void kernelA(const float* __restrict__ x) {
    const int i0  = blockIdx.x;   // 0..63
    const int b   = blockIdx.y;   // 0..255
    const int tid = threadIdx.x;  // 0..255

    __shared__ float S[64 * 64];      // 16 KB input slice
    __shared__ float Bts[64 * 32];    //  8 KB  Bt[i][o]
    __shared__ float Pt[64 * 33];     //  8.45 KB  Pt[j][o1]  (padded)
    __shared__ float Wsm[32 * 33];    //  4.2 KB   W[o1][o2]  (padded)

    // load Bt
    for (int idx = tid; idx < NI * NO; idx += 256) Bts[idx] = g_Bt[idx];

    // load slice (contiguous 4096 floats), float4-coalesced
    const float4* __restrict__ xin =
        reinterpret_cast<const float4*>(x + (size_t)b * 262144 + (size_t)i0 * 4096);
    float4* S4 = reinterpret_cast<float4*>(S);
    #pragma unroll 4
    for (int idx = tid; idx < 1024; idx += 256) S4[idx] = xin[idx];
    __syncthreads();

    // ---- stage P: P[o][j] = sum_i B[o][i] * S[i][j]
    // thread: o = tid&31, jg = tid>>5 (8 j-values: jg*8..jg*8+7)
    {
        const int o  = tid & 31;
        const int jg = tid >> 5;
        unsigned long long acc0 = 0, acc1 = 0, acc2 = 0, acc3 = 0;
        #pragma unroll
        for (int i = 0; i < 64; ++i) {
            unsigned long long bb = packdup(Bts[i * 32 + o]);           // broadcast-safe
            const ulonglong2* srow =
                reinterpret_cast<const ulonglong2*>(&S[i * 64 + jg * 8]); // 32B aligned
            ulonglong2 s01 = srow[0];
            ulonglong2 s23 = srow[1];
            acc0 = ffma2(bb, s01.x, acc0);
            acc1 = ffma2(bb, s01.y, acc1);
            acc2 = ffma2(bb, s23.x, acc2);
            acc3 = ffma2(bb, s23.y, acc3);
        }
        float2 u;
        u = unpack2(acc0); Pt[(jg * 8 + 0) * 33 + o] = u.x; Pt[(jg * 8 + 1) * 33 + o] = u.y;
        u = unpack2(acc1); Pt[(jg * 8 + 2) * 33 + o] = u.x; Pt[(jg * 8 + 3) * 33 + o] = u.y;
        u = unpack2(acc2); Pt[(jg * 8 + 4) * 33 + o] = u.x; Pt[(jg * 8 + 5) * 33 + o] = u.y;
        u = unpack2(acc3); Pt[(jg * 8 + 6) * 33 + o] = u.x; Pt[(jg * 8 + 7) * 33 + o] = u.y;
    }
    __syncthreads();

    // ---- stage W: W[o1][o2] = sum_j P[o1][j] * B[o2][j]
    // thread: o1 = tid&31, w = tid>>5, o2 = w*4 .. w*4+3
    {
        const int o1 = tid & 31;
        const int w  = tid >> 5;
        unsigned long long a0 = 0, a1 = 0;
        #pragma unroll
        for (int j = 0; j < 64; ++j) {
            unsigned long long pv = packdup(Pt[j * 33 + o1]);
            ulonglong2 b2 =
                *reinterpret_cast<const ulonglong2*>(&Bts[j * 32 + w * 4]); // 16B aligned
            a0 = ffma2(pv, b2.x, a0);
            a1 = ffma2(pv, b2.y, a1);
        }
        float2 u;
        u = unpack2(a0); Wsm[o1 * 33 + w * 4 + 0] = u.x; Wsm[o1 * 33 + w * 4 + 1] = u.y;
        u = unpack2(a1); Wsm[o1 * 33 + w * 4 + 2] = u.x; Wsm[o1 * 33 + w * 4 + 3] = u.y;
    }
    __syncthreads();

    // ---- write W to global, coalesced
    float* __restrict__ Wout = g_W + ((size_t)b * 64 + i0) * 1024;
    #pragma unroll 4
    for (int idx = tid; idx < 1024; idx += 256)
        Wout[idx] = Wsm[(idx >> 5) * 33 + (idx & 31)];
}

// ---------------- kernel B: contract i0 ---------------------------------------
// out[b][o0][col] = sum_i0 B[o0][i0] * W[b][i0][col], col = o1*32+o2.
// One CTA per (batch, 128-column chunk cc in 0..7).
__global__ __launch_bounds__(256) void kernelB(float* __restrict__ out) {
    const int cc  = blockIdx.x;   // 0..7
    const int b   = blockIdx.y;   // 0..255
    const int tid = threadIdx.x;

    __shared__ float Ws[64 * 128];                 // 32 KB
    __shared__ unsigned long long Btd[64 * 32];    // 16 KB dup-packed B

    for (int idx = tid; idx < NI * NO; idx += 256)
        Btd[idx] = packdup(g_Bt[idx]);

    // load W chunk: rows 0..63, cols cc*128..cc*128+127
    {
        const float4* __restrict__ src = reinterpret_cast<const float4*>(g_W);
        float4* Ws4 = reinterpret_cast<float4*>(Ws);
        #pragma unroll 8
        for (int idx = tid; idx < 64 * 32; idx += 256) {
            int r = idx >> 5, q = idx & 31;
            Ws4[idx] = src[((size_t)b * 64 + r) * 256 + cc * 32 + q];
        }
    }
    __syncthreads();

    const int lane = tid & 31;     // column group: cols lane*4 .. lane*4+3
    const int w    = tid >> 5;     // o0 group: o0 = w*4 .. w*4+3

    unsigned long long acc[8];     // [o0 local 0..3][col pair 0..1]
    #pragma unroll
    for (int q = 0; q < 8; ++q) acc[q] = 0ULL;

    #pragma unroll
    for (int i = 0; i < 64; ++i) {
        ulonglong2 wv = *reinterpret_cast<const ulonglong2*>(&Ws[i * 128 + lane * 4]);
        ulonglong2 b01 = *reinterpret_cast<const ulonglong2*>(&Btd[i * 32 + w * 4]);
        ulonglong2 b23 = *reinterpret_cast<const ulonglong2*>(&Btd[i * 32 + w * 4 + 2]);
        acc[0] = ffma2(b01.x, wv.x, acc[0]);
        acc[1] = ffma2(b01.x, wv.y, acc[1]);
        acc[2] = ffma2(b01.y, wv.x, acc[2]);
        acc[3] = ffma2(b01.y, wv.y, acc[3]);
        acc[4] = ffma2(b23.x, wv.x, acc[4]);
        acc[5] = ffma2(b23.x, wv.y, acc[5]);
        acc[6] = ffma2(b23.y, wv.x, acc[6]);
        acc[7] = ffma2(b23.y, wv.y, acc[7]);
    }

    // write: out[b][o0][cc*128 + lane*4 .. +3], float4 per o0
    #pragma unroll
    for (int r = 0; r < 4; ++r) {
        float2 u0 = unpack2(acc[r * 2 + 0]);
        float2 u1 = unpack2(acc[r * 2 + 1]);
        float4 v = make_float4(u0.x, u0.y, u1.x, u1.y);
        float* dst = out + ((size_t)b * 32 + (w * 4 + r)) * 1024 + cc * 128 + lane * 4;
        *reinterpret_cast<float4*>(dst) = v;
    }
}

// ---------------- launch -------------------------------------------------------
extern "C" void kernel_launch(void* const* d_in, const int* in_sizes, int n_in,
                              void* d_out, int out_size) {
    const float* x = (const float*)d_in[0];
    float* out = (float*)d_out;

    init_B_kernel<<<8, 256>>>();

    dim3 gA(64, 256);
    kernelA<<<gA, 256>>>(x);

    dim3 gB(8, 256);
    kernelB<<<gB, 256>>>(out);
}

// round 2
// speedup vs baseline: 1.4272x; 1.4272x over previous
#include <cuda_runtime.h>
#include <math.h>

// ----------------------------------------------------------------------------
// SpectralPooling: x (8,32,64,64,64) fp32
//   y = idctn( pad( crop( dctn(x) ) ) )
// DCTs along axes 0,1 cancel (orthonormal; crop/pad touches only axes 2-4).
// Remaining op: per 256 batches, apply B (32x64) along each of last 3 axes,
// B = D32c^T @ D64c with D32c = dct_mat(32)[:28,:], D64c = dct_mat(64)[:28,:].
// ----------------------------------------------------------------------------

#define NBATCH 256
#define NI 64      // input axis length
#define NO 32      // output axis length

// B stored transposed: g_Bt[i*32 + o] = B[o][i]
__device__ float g_Bt[NI * NO];

// scratch: W[b][i0][o1*32+o2]  (256 * 64 * 1024 floats = 64 MB)
__device__ float g_W[NBATCH * NI * NO * NO];

// ---------------- packed f32x2 helpers (FFMA2: 2 FMA / instr) ----------------
__device__ __forceinline__ unsigned long long ffma2(unsigned long long a,
                                                    unsigned long long b,
                                                    unsigned long long c) {
    unsigned long long d;
    asm("fma.rn.f32x2 %0, %1, %2, %3;" : "=l"(d) : "l"(a), "l"(b), "l"(c));
    return d;
}
__device__ __forceinline__ unsigned long long packdup(float v) {
    unsigned long long r;
    asm("mov.b64 %0, {%1, %1};" : "=l"(r) : "r"(__float_as_uint(v)));
    return r;
}
__device__ __forceinline__ float2 unpack2(unsigned long long v) {
    unsigned lo, hi;
    asm("mov.b64 {%0, %1}, %2;" : "=r"(lo), "=r"(hi) : "l"(v));
    float2 f;
    f.x = __uint_as_float(lo);
    f.y = __uint_as_float(hi);
    return f;
}

// ---------------- init: fp32 cospif (exact rational args, ~2ulp) --------------
__global__ void init_B_kernel() {
    int idx = blockIdx.x * blockDim.x + threadIdx.x;   // 0..2047
    if (idx >= NI * NO) return;
    int i = idx >> 5;   // input index 0..63
    int o = idx & 31;   // output index 0..31
    const float s32_0 = 0.17677669529663688f;  // sqrt(1/32)
    const float s32_k = 0.25f;                 // sqrt(2/32)
    const float s64_0 = 0.125f;                // sqrt(1/64)
    const float s64_k = 0.17677669529663688f;  // sqrt(2/64)
    float s = 0.0f;
    #pragma unroll
    for (int k = 0; k < 28; ++k) {
        float a32 = (2.0f * o + 1.0f) * (float)k / 64.0f;
        float a64 = (2.0f * i + 1.0f) * (float)k / 128.0f;
        float d32 = ((k == 0) ? s32_0 : s32_k) * cospif(a32);
        float d64 = ((k == 0) ? s64_0 : s64_k) * cospif(a64);
        s += d32 * d64;
    }
    g_Bt[idx] = s;
}

// ---------------- kernel A: 2 slices per CTA, fuse i2 & i1 contractions -------
// CTA (i0p, b): slices i0 = 2*i0p, 2*i0p+1. For each slice S[64][64]:
//   P = B @ S      (stage P, contract i2... actually i1? symmetric, fine)
//   W = P @ B^T    (stage W)
// Pt is aliased into the (dead) S buffer after stage P. W written straight
// to g_W from registers.
__global__ __launch_bounds__(256) void kernelA(const float* __restrict__ x) {
    const int i0p = blockIdx.x;   // 0..31
    const int b   = blockIdx.y;   // 0..255
    const int tid = threadIdx.x;  // 0..255

    __shared__ float S[2 * 4096];   // 32 KB; reused as Pt[2][64*33] after stage P
    __shared__ float Bts[NI * NO];  //  8 KB  Bt[i][o]

    for (int idx = tid; idx < NI * NO; idx += 256) Bts[idx] = g_Bt[idx];

    // load both slices (8192 contiguous floats), float4-coalesced
    const float4* __restrict__ xin =
        reinterpret_cast<const float4*>(x + (size_t)b * 262144 + (size_t)i0p * 8192);
    float4* S4 = reinterpret_cast<float4*>(S);
    #pragma unroll 8
    for (int idx = tid; idx < 2048; idx += 256) S4[idx] = xin[idx];
    __syncthreads();

    // ---- stage P: P[o][j] = sum_i B[o][i] * S[i][j], both slices
    // thread: o = tid&31 (warp-uniform jg => Bt load is broadcast)
    const int o  = tid & 31;
    const int jg = tid >> 5;   // j block: jg*8 .. jg*8+7
    unsigned long long acc[2][4];
    #pragma unroll
    for (int s = 0; s < 2; ++s)
        #pragma unroll
        for (int q = 0; q < 4; ++q) acc[s][q] = 0ULL;

    #pragma unroll
    for (int i = 0; i < 64; ++i) {
        unsigned long long bb = packdup(Bts[i * 32 + o]);   // broadcast
        #pragma unroll
        for (int s = 0; s < 2; ++s) {
            const ulonglong2* srow =
                reinterpret_cast<const ulonglong2*>(&S[s * 4096 + i * 64 + jg * 8]);
            ulonglong2 s01 = srow[0];
            ulonglong2 s23 = srow[1];
            acc[s][0] = ffma2(bb, s01.x, acc[s][0]);
            acc[s][1] = ffma2(bb, s01.y, acc[s][1]);
            acc[s][2] = ffma2(bb, s23.x, acc[s][2]);
            acc[s][3] = ffma2(bb, s23.y, acc[s][3]);
        }
    }
    __syncthreads();   // S fully consumed; safe to alias

    // Pt[s][j*33 + o], slice stride 2112 floats (64*33)
    float* Pt = S;
    #pragma unroll
    for (int s = 0; s < 2; ++s) {
        float2 u;
        u = unpack2(acc[s][0]);
        Pt[s * 2112 + (jg * 8 + 0) * 33 + o] = u.x;
        Pt[s * 2112 + (jg * 8 + 1) * 33 + o] = u.y;
        u = unpack2(acc[s][1]);
        Pt[s * 2112 + (jg * 8 + 2) * 33 + o] = u.x;
        Pt[s * 2112 + (jg * 8 + 3) * 33 + o] = u.y;
        u = unpack2(acc[s][2]);
        Pt[s * 2112 + (jg * 8 + 4) * 33 + o] = u.x;
        Pt[s * 2112 + (jg * 8 + 5) * 33 + o] = u.y;
        u = unpack2(acc[s][3]);
        Pt[s * 2112 + (jg * 8 + 6) * 33 + o] = u.x;
        Pt[s * 2112 + (jg * 8 + 7) * 33 + o] = u.y;
    }
    __syncthreads();

    // ---- stage W: W[o1][o2] = sum_j P[o1][j] * B[o2][j], both slices
    // thread: o1 = tid&31, w = tid>>5 (o2 = w*4..w*4+3; B load broadcast)
    const int o1 = tid & 31;
    const int w  = tid >> 5;
    unsigned long long a[2][2];
    a[0][0] = a[0][1] = a[1][0] = a[1][1] = 0ULL;

    #pragma unroll
    for (int j = 0; j < 64; ++j) {
        ulonglong2 b2 =
            *reinterpret_cast<const ulonglong2*>(&Bts[j * 32 + w * 4]);  // broadcast
        #pragma unroll
        for (int s = 0; s < 2; ++s) {
            unsigned long long pv = packdup(Pt[s * 2112 + j * 33 + o1]); // conflict-free
            a[s][0] = ffma2(pv, b2.x, a[s][0]);
            a[s][1] = ffma2(pv, b2.y, a[s][1]);
        }
    }

    // direct global write; each 128B line filled cooperatively by the 8 warps
    #pragma unroll
    for (int s = 0; s < 2; ++s) {
        float2 u0 = unpack2(a[s][0]);
        float2 u1 = unpack2(a[s][1]);
        float4 v = make_float4(u0.x, u0.y, u1.x, u1.y);
        float* dst = g_W + ((size_t)b * 64 + (size_t)(i0p * 2 + s)) * 1024
                         + o1 * 32 + w * 4;
        *reinterpret_cast<float4*>(dst) = v;
    }
}

// ---------------- kernel B: contract i0 ---------------------------------------
// out[b][o0][col] = sum_i0 B[o0][i0] * W[b][i0][col], col = o1*32+o2.
// One CTA per (batch, 128-column chunk cc in 0..7).
__global__ __launch_bounds__(256) void kernelB(float* __restrict__ out) {
    const int cc  = blockIdx.x;   // 0..7
    const int b   = blockIdx.y;   // 0..255
    const int tid = threadIdx.x;

    __shared__ float Ws[64 * 128];                 // 32 KB
    __shared__ unsigned long long Btd[64 * 32];    // 16 KB dup-packed B

    for (int idx = tid; idx < NI * NO; idx += 256)
        Btd[idx] = packdup(g_Bt[idx]);

    // load W chunk: rows 0..63, cols cc*128..cc*128+127
    {
        const float4* __restrict__ src = reinterpret_cast<const float4*>(g_W);
        float4* Ws4 = reinterpret_cast<float4*>(Ws);
        #pragma unroll 8
        for (int idx = tid; idx < 64 * 32; idx += 256) {
            int r = idx >> 5, q = idx & 31;
            Ws4[idx] = src[((size_t)b * 64 + r) * 256 + cc * 32 + q];
        }
    }
    __syncthreads();

    const int lane = tid & 31;     // column group: cols lane*4 .. lane*4+3
    const int w    = tid >> 5;     // o0 group: o0 = w*4 .. w*4+3

    unsigned long long acc[8];     // [o0 local 0..3][col pair 0..1]
    #pragma unroll
    for (int q = 0; q < 8; ++q) acc[q] = 0ULL;

    #pragma unroll
    for (int i = 0; i < 64; ++i) {
        ulonglong2 wv = *reinterpret_cast<const ulonglong2*>(&Ws[i * 128 + lane * 4]);
        ulonglong2 b01 = *reinterpret_cast<const ulonglong2*>(&Btd[i * 32 + w * 4]);
        ulonglong2 b23 = *reinterpret_cast<const ulonglong2*>(&Btd[i * 32 + w * 4 + 2]);
        acc[0] = ffma2(b01.x, wv.x, acc[0]);
        acc[1] = ffma2(b01.x, wv.y, acc[1]);
        acc[2] = ffma2(b01.y, wv.x, acc[2]);
        acc[3] = ffma2(b01.y, wv.y, acc[3]);
        acc[4] = ffma2(b23.x, wv.x, acc[4]);
        acc[5] = ffma2(b23.x, wv.y, acc[5]);
        acc[6] = ffma2(b23.y, wv.x, acc[6]);
        acc[7] = ffma2(b23.y, wv.y, acc[7]);
    }

    // write: out[b][o0][cc*128 + lane*4 .. +3], float4 per o0
    #pragma unroll
    for (int r = 0; r < 4; ++r) {
        float2 u0 = unpack2(acc[r * 2 + 0]);
        float2 u1 = unpack2(acc[r * 2 + 1]);
        float4 v = make_float4(u0.x, u0.y, u1.x, u1.y);
        float* dst = out + ((size_t)b * 32 + (w * 4 + r)) * 1024 + cc * 128 + lane * 4;
        *reinterpret_cast<float4*>(dst) = v;
    }
}

// ---------------- launch -------------------------------------------------------
extern "C" void kernel_launch(void* const* d_in, const int* in_sizes, int n_in,
                              void* d_out, int out_size) {
    const float* x = (const float*)d_in[0];
    float* out = (float*)d_out;

    init_B_kernel<<<8, 256>>>();

    dim3 gA(32, 256);
    kernelA<<<gA, 256>>>(x);

    dim3 gB(8, 256);
    kernelB<<<gB, 256>>>(out);
}

// round 4
// speedup vs baseline: 2.8282x; 1.9817x over previous
#include <cuda_runtime.h>
#include <cuda_bf16.h>
#include <stdint.h>

// ----------------------------------------------------------------------------
// SpectralPooling via HMMA (mma.sync m16n8k16 bf16, 3-term split) GEMMs.
// y = idctn(pad(crop(dctn(x)))); axes 0,1 cancel. Per-axis operator
// B[o][i] = sum_{k<28} D32[k,o]*D64[k,i]  (32x64), applied along axes 2,3,4.
// Three stages, each GEMM [rows x 64] -> [rows x 32] against B^T; outputs are
// written "pre-transposed" so K is always contiguous and stores coalesce:
//   stage1 (SB=12): X[b][i0][i1][i2]   -> T1[b][o2][i0][i1]
//   stage2 (SB=11): T1[b][o2][i0][i1]  -> T2[b][o1][o2][i0]
//   stage3 (SB=10): T2[b][o1][o2][i0]  -> Y[b][o0][o1][o2]
// out_addr(m,c) = (m>>SB)*(32<<SB) + c*(1<<SB) + (m & ((1<<SB)-1))
// Precision: D = Ah*Bh + Ah*Bl + Al*Bh (bf16 hi/lo splits, fp32 accumulate).
// ----------------------------------------------------------------------------

__device__ __nv_bfloat16 g_Bh[2048];   // B hi, row-major [o][i] (32x64)
__device__ __nv_bfloat16 g_Bl[2048];   // B lo
__device__ float g_T1[33554432];       // 128 MB scratch
__device__ float g_T2[16777216];       //  64 MB scratch

// ---------------- init: B and its bf16 hi/lo split -----------------------------
__global__ void init_B_kernel() {
    int idx = blockIdx.x * blockDim.x + threadIdx.x;
    if (idx >= 2048) return;
    int o = idx >> 6;   // 0..31
    int i = idx & 63;   // 0..63
    const float s32_0 = 0.17677669529663688f;  // sqrt(1/32)
    const float s32_k = 0.25f;                 // sqrt(2/32)
    const float s64_0 = 0.125f;                // sqrt(1/64)
    const float s64_k = 0.17677669529663688f;  // sqrt(2/64)
    float s = 0.0f;
    #pragma unroll
    for (int k = 0; k < 28; ++k) {
        float a32 = (2.0f * o + 1.0f) * (float)k / 64.0f;
        float a64 = (2.0f * i + 1.0f) * (float)k / 128.0f;
        float d32 = ((k == 0) ? s32_0 : s32_k) * cospif(a32);
        float d64 = ((k == 0) ? s64_0 : s64_k) * cospif(a64);
        s += d32 * d64;
    }
    __nv_bfloat16 h = __float2bfloat16(s);
    float lo = s - __bfloat162float(h);
    g_Bh[idx] = h;
    g_Bl[idx] = __float2bfloat16(lo);
}

// ---------------- mma.sync wrapper ----------------------------------------------
__device__ __forceinline__ void mma16816(float* d, const uint32_t* a,
                                         const uint32_t* b) {
    asm("mma.sync.aligned.m16n8k16.row.col.f32.bf16.bf16.f32 "
        "{%0,%1,%2,%3}, {%4,%5,%6,%7}, {%8,%9}, {%0,%1,%2,%3};"
        : "+f"(d[0]), "+f"(d[1]), "+f"(d[2]), "+f"(d[3])
        : "r"(a[0]), "r"(a[1]), "r"(a[2]), "r"(a[3]), "r"(b[0]), "r"(b[1]));
}

// ---------------- stage kernel --------------------------------------------------
// A tile: 128 rows x 64 K (fp32 in, split to bf16 hi/lo in smem, row stride 72).
// Warp w computes rows w*32..w*32+31, all 32 output cols.
template<int SB>
__global__ __launch_bounds__(128) void stage_kernel(const float* __restrict__ xin,
                                                    float* __restrict__ xout) {
    const float* in = (SB == 12) ? xin : (SB == 11 ? (const float*)g_T1
                                                   : (const float*)g_T2);
    float* out      = (SB == 12) ? (float*)g_T1
                                 : (SB == 11 ? (float*)g_T2 : xout);
    constexpr size_t OC = (size_t)1 << SB;

    __shared__ __align__(16) __nv_bfloat16 sAh[128 * 72];  // 18 KB
    __shared__ __align__(16) __nv_bfloat16 sAl[128 * 72];  // 18 KB
    __shared__ __align__(16) __nv_bfloat16 sBh[32 * 72];   // 4.5 KB
    __shared__ __align__(16) __nv_bfloat16 sBl[32 * 72];   // 4.5 KB

    const int tid = threadIdx.x;
    const int w   = tid >> 5;
    const int lid = tid & 31;
    const int gid = lid >> 2;   // 0..7
    const int tg  = lid & 3;    // 0..3

    // ---- load B hi/lo into padded smem (row stride 144 B)
    {
        const uint32_t* bh = (const uint32_t*)g_Bh;
        const uint32_t* bl = (const uint32_t*)g_Bl;
        #pragma unroll
        for (int idx = tid; idx < 1024; idx += 128) {      // 1024 bf16-pairs
            int r = idx >> 5, c2 = idx & 31;               // row, pair-in-row
            *(uint32_t*)((char*)sBh + r * 144 + c2 * 4) = bh[idx];
            *(uint32_t*)((char*)sBl + r * 144 + c2 * 4) = bl[idx];
        }
    }

    // ---- load A tile (2048 float4), split to bf16 hi/lo, padded smem
    {
        const float4* __restrict__ inp =
            (const float4*)(in + (size_t)blockIdx.x * 8192);
        #pragma unroll
        for (int j = 0; j < 16; ++j) {
            int f = j * 128 + tid;           // float4 index 0..2047
            float4 v = inp[f];
            int r = f >> 4, k4 = f & 15;     // row, float4-in-row
            uint32_t h01, h23, l01, l23;
            asm("cvt.rn.bf16x2.f32 %0, %1, %2;" : "=r"(h01) : "f"(v.y), "f"(v.x));
            asm("cvt.rn.bf16x2.f32 %0, %1, %2;" : "=r"(h23) : "f"(v.w), "f"(v.z));
            float hx = __uint_as_float(h01 << 16);
            float hy = __uint_as_float(h01 & 0xFFFF0000u);
            float hz = __uint_as_float(h23 << 16);
            float hw = __uint_as_float(h23 & 0xFFFF0000u);
            asm("cvt.rn.bf16x2.f32 %0, %1, %2;" : "=r"(l01)
                : "f"(v.y - hy), "f"(v.x - hx));
            asm("cvt.rn.bf16x2.f32 %0, %1, %2;" : "=r"(l23)
                : "f"(v.w - hw), "f"(v.z - hz));
            *(uint2*)((char*)sAh + r * 144 + k4 * 8) = make_uint2(h01, h23);
            *(uint2*)((char*)sAl + r * 144 + k4 * 8) = make_uint2(l01, l23);
        }
    }
    __syncthreads();

    // ---- HMMA mainloop: acc[rt][nt][4], rt = row-tile(16), nt = n-tile(8)
    float acc[2][4][4];
    #pragma unroll
    for (int rt = 0; rt < 2; ++rt)
        #pragma unroll
        for (int nt = 0; nt < 4; ++nt)
            #pragma unroll
            for (int q = 0; q < 4; ++q) acc[rt][nt][q] = 0.0f;

    #pragma unroll
    for (int kk = 0; kk < 4; ++kk) {          // k-step of 16
        uint32_t ah[2][4], al[2][4];
        #pragma unroll
        for (int rt = 0; rt < 2; ++rt) {
            int row = w * 32 + rt * 16 + gid;
            const char* pH = (const char*)sAh + row * 144 + kk * 32 + tg * 4;
            const char* pL = (const char*)sAl + row * 144 + kk * 32 + tg * 4;
            ah[rt][0] = *(const uint32_t*)(pH);
            ah[rt][1] = *(const uint32_t*)(pH + 8 * 144);
            ah[rt][2] = *(const uint32_t*)(pH + 16);
            ah[rt][3] = *(const uint32_t*)(pH + 8 * 144 + 16);
            al[rt][0] = *(const uint32_t*)(pL);
            al[rt][1] = *(const uint32_t*)(pL + 8 * 144);
            al[rt][2] = *(const uint32_t*)(pL + 16);
            al[rt][3] = *(const uint32_t*)(pL + 8 * 144 + 16);
        }
        uint32_t bh[4][2], bl[4][2];
        #pragma unroll
        for (int nt = 0; nt < 4; ++nt) {
            int n = nt * 8 + gid;
            const char* pH = (const char*)sBh + n * 144 + kk * 32 + tg * 4;
            const char* pL = (const char*)sBl + n * 144 + kk * 32 + tg * 4;
            bh[nt][0] = *(const uint32_t*)(pH);
            bh[nt][1] = *(const uint32_t*)(pH + 16);
            bl[nt][0] = *(const uint32_t*)(pL);
            bl[nt][1] = *(const uint32_t*)(pL + 16);
        }
        #pragma unroll
        for (int rt = 0; rt < 2; ++rt)
            #pragma unroll
            for (int nt = 0; nt < 4; ++nt) {
                mma16816(acc[rt][nt], ah[rt], bh[nt]);   // Ah*Bh
                mma16816(acc[rt][nt], ah[rt], bl[nt]);   // Ah*Bl
                mma16816(acc[rt][nt], al[rt], bh[nt]);   // Al*Bh
            }
    }

    // ---- epilogue: transpose through this warp's own (dead) A region
    __syncwarp();
    float* ep = (float*)((char*)sAh + (size_t)w * 32 * 144);   // 32x33 fp32 fits
    #pragma unroll
    for (int rt = 0; rt < 2; ++rt)
        #pragma unroll
        for (int nt = 0; nt < 4; ++nt) {
            int r0 = rt * 16 + gid;
            int c0 = nt * 8 + tg * 2;
            ep[r0 * 33 + c0]           = acc[rt][nt][0];
            ep[r0 * 33 + c0 + 1]       = acc[rt][nt][1];
            ep[(r0 + 8) * 33 + c0]     = acc[rt][nt][2];
            ep[(r0 + 8) * 33 + c0 + 1] = acc[rt][nt][3];
        }
    __syncwarp();

    // ---- coalesced transposed store
    size_t m = (size_t)blockIdx.x * 128 + (size_t)(w * 32 + lid);
    float* __restrict__ ob = out + (m >> SB) * (OC * 32) + (m & (OC - 1));
    #pragma unroll
    for (int c = 0; c < 32; ++c)
        ob[(size_t)c << SB] = ep[lid * 33 + c];
}

// ---------------- launch ---------------------------------------------------------
extern "C" void kernel_launch(void* const* d_in, const int* in_sizes, int n_in,
                              void* d_out, int out_size) {
    const float* x = (const float*)d_in[0];
    float* out = (float*)d_out;

    init_B_kernel<<<16, 128>>>();

    stage_kernel<12><<<8192, 128>>>(x, out);   // X  -> T1   (contract i2)
    stage_kernel<11><<<4096, 128>>>(x, out);   // T1 -> T2   (contract i1)
    stage_kernel<10><<<2048, 128>>>(x, out);   // T2 -> out  (contract i0)
}